// round 1
// baseline (speedup 1.0000x reference)
#include <cuda_runtime.h>

// ---------------------------------------------------------------------------
// WMSA (3D shifted-window attention), fp32 baseline.
//   B=2, S=32^3, C=192 (6 heads x 32), WIN=4 -> nw=8, 512 windows/batch,
//   64 tokens/window. SHIFT=2 cyclic shift with boundary mask.
// Pipeline:
//   K1: roll(-2)+window gather fused into QKV GEMM  (M=65536,K=192,N=576)
//   K2: per (window,head) attention: QK^T*scale + rel-bias + shift-mask,
//       softmax, PV
//   K3: out-proj GEMM (M=65536,K=192,N=192) with inverse window + roll(+2)
// ---------------------------------------------------------------------------

#define NWINS 1024              // B * nw^3 = 2 * 512
#define TPW   64                // tokens per window (4^3)

__device__ float g_qkv[(size_t)NWINS * TPW * 576];   // [bw][tok][576]  (q|k|v)
__device__ float g_att[(size_t)NWINS * TPW * 192];   // [bw][tok][192]

// ------------------------------ K1: QKV GEMM -------------------------------
// grid (1024, 9), block 256. 64x64 tile, K chunks of 64 (3 chunks).
__global__ __launch_bounds__(256) void qkv_kernel(
    const float* __restrict__ x, const float* __restrict__ Wqkv,
    const float* __restrict__ bqkv)
{
    __shared__ float As[64 * 68];   // A transposed: [k][token]
    __shared__ float Bs[64 * 68];   // [k][n]

    const int bw = blockIdx.x, nt = blockIdx.y;
    const int b = bw >> 9, w = bw & 511;
    const int wz = w >> 6, wy = (w >> 3) & 7, wx = w & 7;
    const int tid = threadIdx.x;
    const int lane16 = tid & 15, grp = tid >> 4;
    const int r0 = grp * 4, c0 = lane16 * 4;

    float acc[4][4] = {};

    for (int kc = 0; kc < 3; ++kc) {
        __syncthreads();
        // load A chunk: 64 tokens x 64 k (gather with roll -2 + window map)
        #pragma unroll
        for (int pass = 0; pass < 4; ++pass) {
            int tok = grp + pass * 16;
            int tz = tok >> 4, tyy = (tok >> 2) & 3, txx = tok & 3;
            int z  = (wz * 4 + tz  + 2) & 31;
            int y  = (wy * 4 + tyy + 2) & 31;
            int xx = (wx * 4 + txx + 2) & 31;
            const float4 a4 = *(const float4*)&x[((((size_t)b * 32 + z) * 32 + y) * 32 + xx) * 192
                                                 + kc * 64 + lane16 * 4];
            As[(lane16 * 4 + 0) * 68 + tok] = a4.x;
            As[(lane16 * 4 + 1) * 68 + tok] = a4.y;
            As[(lane16 * 4 + 2) * 68 + tok] = a4.z;
            As[(lane16 * 4 + 3) * 68 + tok] = a4.w;
        }
        // load B chunk: Wqkv rows kc*64..+63, cols nt*64..+63
        #pragma unroll
        for (int pass = 0; pass < 4; ++pass) {
            int row = grp + pass * 16;
            *(float4*)&Bs[row * 68 + lane16 * 4] =
                *(const float4*)&Wqkv[(size_t)(kc * 64 + row) * 576 + nt * 64 + lane16 * 4];
        }
        __syncthreads();
        #pragma unroll 4
        for (int kk = 0; kk < 64; ++kk) {
            float4 a = *(float4*)&As[kk * 68 + r0];
            float4 bb = *(float4*)&Bs[kk * 68 + c0];
            acc[0][0] += a.x * bb.x; acc[0][1] += a.x * bb.y; acc[0][2] += a.x * bb.z; acc[0][3] += a.x * bb.w;
            acc[1][0] += a.y * bb.x; acc[1][1] += a.y * bb.y; acc[1][2] += a.y * bb.z; acc[1][3] += a.y * bb.w;
            acc[2][0] += a.z * bb.x; acc[2][1] += a.z * bb.y; acc[2][2] += a.z * bb.z; acc[2][3] += a.z * bb.w;
            acc[3][0] += a.w * bb.x; acc[3][1] += a.w * bb.y; acc[3][2] += a.w * bb.z; acc[3][3] += a.w * bb.w;
        }
    }
    #pragma unroll
    for (int i = 0; i < 4; ++i) {
        size_t base = ((size_t)bw * 64 + (r0 + i)) * 576 + nt * 64;
        #pragma unroll
        for (int j = 0; j < 4; ++j)
            g_qkv[base + c0 + j] = acc[i][j] + bqkv[nt * 64 + c0 + j];
    }
}

// ------------------------------ K2: attention ------------------------------
// grid (1024, 6), block 256.
__global__ __launch_bounds__(256) void attn_kernel(const float* __restrict__ relp)
{
    __shared__ float qkT[2 * 32 * 68];   // qT[32][68] | kT[32][68]; aliased as pT[64][66]
    __shared__ float vS[64 * 36];        // [q][c]
    __shared__ float simS[64 * 66];      // [p][q]
    __shared__ float relS[343];

    const int bw = blockIdx.x, h = blockIdx.y;
    const int w = bw & 511;
    const int wz = w >> 6, wy = (w >> 3) & 7, wx = w & 7;
    const int tid = threadIdx.x;
    const float scale = 0.17677669529663687f;   // 32^-0.5

    for (int i = tid; i < 343; i += 256) relS[i] = relp[h * 343 + i];

    {   // load q (transposed), k (transposed), v (row-major)
        int lane8 = tid & 7, rg = tid >> 3;
        int cc = lane8 * 4;
        #pragma unroll
        for (int pass = 0; pass < 2; ++pass) {
            int row = rg + pass * 32;
            size_t base = ((size_t)bw * 64 + row) * 576;
            float4 qv = *(const float4*)&g_qkv[base + h * 32 + cc];
            float4 kv = *(const float4*)&g_qkv[base + 192 + h * 32 + cc];
            float4 vv = *(const float4*)&g_qkv[base + 384 + h * 32 + cc];
            qkT[(cc + 0) * 68 + row] = qv.x;
            qkT[(cc + 1) * 68 + row] = qv.y;
            qkT[(cc + 2) * 68 + row] = qv.z;
            qkT[(cc + 3) * 68 + row] = qv.w;
            qkT[2176 + (cc + 0) * 68 + row] = kv.x;
            qkT[2176 + (cc + 1) * 68 + row] = kv.y;
            qkT[2176 + (cc + 2) * 68 + row] = kv.z;
            qkT[2176 + (cc + 3) * 68 + row] = kv.w;
            *(float4*)&vS[row * 36 + cc] = vv;
        }
    }
    __syncthreads();

    // phase 1: sim = q @ k^T, + bias, mask
    {
        int ty = tid >> 4, tx = tid & 15;
        int r0 = ty * 4, c0 = tx * 4;
        float acc[4][4] = {};
        #pragma unroll 4
        for (int kk = 0; kk < 32; ++kk) {
            float4 a  = *(float4*)&qkT[kk * 68 + r0];
            float4 bb = *(float4*)&qkT[2176 + kk * 68 + c0];
            acc[0][0] += a.x * bb.x; acc[0][1] += a.x * bb.y; acc[0][2] += a.x * bb.z; acc[0][3] += a.x * bb.w;
            acc[1][0] += a.y * bb.x; acc[1][1] += a.y * bb.y; acc[1][2] += a.y * bb.z; acc[1][3] += a.y * bb.w;
            acc[2][0] += a.z * bb.x; acc[2][1] += a.z * bb.y; acc[2][2] += a.z * bb.z; acc[2][3] += a.z * bb.w;
            acc[3][0] += a.w * bb.x; acc[3][1] += a.w * bb.y; acc[3][2] += a.w * bb.z; acc[3][3] += a.w * bb.w;
        }
        #pragma unroll
        for (int i = 0; i < 4; ++i) {
            int p = r0 + i;
            int pz = p >> 4, py = (p >> 2) & 3, px = p & 3;
            #pragma unroll
            for (int j = 0; j < 4; ++j) {
                int q = c0 + j;
                int qz = q >> 4, qy = (q >> 2) & 3, qx = q & 3;
                bool msk = (wz == 7 && ((pz < 2) != (qz < 2))) ||
                           (wy == 7 && ((py < 2) != (qy < 2))) ||
                           (wx == 7 && ((px < 2) != (qx < 2)));
                float bias = relS[((pz - qz + 3) * 7 + (py - qy + 3)) * 7 + (px - qx + 3)];
                simS[p * 66 + q] = msk ? -1e30f : acc[i][j] * scale + bias;
            }
        }
    }
    __syncthreads();

    // phase 2: softmax per row, write probs TRANSPOSED into qkT (pT[q][p], stride 66)
    {
        int warp = tid >> 5, lane = tid & 31;
        #pragma unroll
        for (int rr = 0; rr < 8; ++rr) {
            int r = warp * 8 + rr;
            float x0 = simS[r * 66 + lane];
            float x1 = simS[r * 66 + 32 + lane];
            float m = fmaxf(x0, x1);
            #pragma unroll
            for (int off = 16; off; off >>= 1)
                m = fmaxf(m, __shfl_xor_sync(0xffffffffu, m, off));
            float e0 = __expf(x0 - m), e1 = __expf(x1 - m);
            float s = e0 + e1;
            #pragma unroll
            for (int off = 16; off; off >>= 1)
                s += __shfl_xor_sync(0xffffffffu, s, off);
            float inv = 1.0f / s;
            qkT[lane * 66 + r]        = e0 * inv;
            qkT[(lane + 32) * 66 + r] = e1 * inv;
        }
    }
    __syncthreads();

    // phase 3: out = probs @ v  (64x32), thread tile 2x4
    {
        int ty3 = tid >> 3, tx3 = tid & 7;
        int p0 = ty3 * 2, cc = tx3 * 4;
        float o[2][4] = {};
        #pragma unroll 4
        for (int q = 0; q < 64; ++q) {
            float a0 = qkT[q * 66 + p0];
            float a1 = qkT[q * 66 + p0 + 1];
            float4 bv = *(float4*)&vS[q * 36 + cc];
            o[0][0] += a0 * bv.x; o[0][1] += a0 * bv.y; o[0][2] += a0 * bv.z; o[0][3] += a0 * bv.w;
            o[1][0] += a1 * bv.x; o[1][1] += a1 * bv.y; o[1][2] += a1 * bv.z; o[1][3] += a1 * bv.w;
        }
        #pragma unroll
        for (int i = 0; i < 2; ++i) {
            size_t base = ((size_t)bw * 64 + (p0 + i)) * 192 + h * 32 + cc;
            #pragma unroll
            for (int j = 0; j < 4; ++j) g_att[base + j] = o[i][j];
        }
    }
}

// ------------------------------ K3: out proj -------------------------------
// grid (1024, 3), block 256. Same GEMM shape; epilogue scatters with inverse
// window map + roll(+2) (identical index map to the input gather).
__global__ __launch_bounds__(256) void proj_kernel(
    const float* __restrict__ Wout, const float* __restrict__ bout,
    float* __restrict__ out)
{
    __shared__ float As[64 * 68];
    __shared__ float Bs[64 * 68];

    const int bw = blockIdx.x, nt = blockIdx.y;
    const int b = bw >> 9, w = bw & 511;
    const int wz = w >> 6, wy = (w >> 3) & 7, wx = w & 7;
    const int tid = threadIdx.x;
    const int lane16 = tid & 15, grp = tid >> 4;
    const int r0 = grp * 4, c0 = lane16 * 4;

    float acc[4][4] = {};

    for (int kc = 0; kc < 3; ++kc) {
        __syncthreads();
        #pragma unroll
        for (int pass = 0; pass < 4; ++pass) {
            int tok = grp + pass * 16;
            float4 a4 = *(const float4*)&g_att[((size_t)bw * 64 + tok) * 192 + kc * 64 + lane16 * 4];
            As[(lane16 * 4 + 0) * 68 + tok] = a4.x;
            As[(lane16 * 4 + 1) * 68 + tok] = a4.y;
            As[(lane16 * 4 + 2) * 68 + tok] = a4.z;
            As[(lane16 * 4 + 3) * 68 + tok] = a4.w;
            int row = grp + pass * 16;
            *(float4*)&Bs[row * 68 + lane16 * 4] =
                *(const float4*)&Wout[(size_t)(kc * 64 + row) * 192 + nt * 64 + lane16 * 4];
        }
        __syncthreads();
        #pragma unroll 4
        for (int kk = 0; kk < 64; ++kk) {
            float4 a = *(float4*)&As[kk * 68 + r0];
            float4 bb = *(float4*)&Bs[kk * 68 + c0];
            acc[0][0] += a.x * bb.x; acc[0][1] += a.x * bb.y; acc[0][2] += a.x * bb.z; acc[0][3] += a.x * bb.w;
            acc[1][0] += a.y * bb.x; acc[1][1] += a.y * bb.y; acc[1][2] += a.y * bb.z; acc[1][3] += a.y * bb.w;
            acc[2][0] += a.z * bb.x; acc[2][1] += a.z * bb.y; acc[2][2] += a.z * bb.z; acc[2][3] += a.z * bb.w;
            acc[3][0] += a.w * bb.x; acc[3][1] += a.w * bb.y; acc[3][2] += a.w * bb.z; acc[3][3] += a.w * bb.w;
        }
    }
    #pragma unroll
    for (int i = 0; i < 4; ++i) {
        int t = r0 + i;
        int tz = t >> 4, tyy = (t >> 2) & 3, txx = t & 3;
        int z  = (wz * 4 + tz  + 2) & 31;
        int y  = (wy * 4 + tyy + 2) & 31;
        int xx = (wx * 4 + txx + 2) & 31;
        size_t base = ((((size_t)b * 32 + z) * 32 + y) * 32 + xx) * 192 + nt * 64;
        #pragma unroll
        for (int j = 0; j < 4; ++j)
            out[base + c0 + j] = acc[i][j] + bout[nt * 64 + c0 + j];
    }
}

// ------------------------------- launch ------------------------------------
extern "C" void kernel_launch(void* const* d_in, const int* in_sizes, int n_in,
                              void* d_out, int out_size)
{
    const float* x    = (const float*)d_in[0];
    const float* Wqkv = (const float*)d_in[1];
    const float* bqkv = (const float*)d_in[2];
    const float* relp = (const float*)d_in[3];
    const float* Wout = (const float*)d_in[4];
    const float* bout = (const float*)d_in[5];
    float* out = (float*)d_out;

    qkv_kernel<<<dim3(1024, 9), 256>>>(x, Wqkv, bqkv);
    attn_kernel<<<dim3(1024, 6), 256>>>(relp);
    proj_kernel<<<dim3(1024, 3), 256>>>(Wout, bout, out);
}

// round 3
// speedup vs baseline: 1.1057x; 1.1057x over previous
#include <cuda_runtime.h>

// ---------------------------------------------------------------------------
// WMSA (3D shifted-window attention), fp32, round 2.
//   K1/K3: 128x64 block tiles, 8x8 register micro-tiles (128 threads),
//          K-chunks of 32 with register-prefetch pipelining.
//   K2: unchanged from round 1 (known correct).
// ---------------------------------------------------------------------------

#define NWINS 1024
#define TPW   64

__device__ float g_qkv[(size_t)NWINS * TPW * 576];   // [row][576] (q|k|v)
__device__ float g_att[(size_t)NWINS * TPW * 192];   // [row][192]

// ------------------------------ K1: QKV GEMM -------------------------------
// M=65536, K=192, N=576. grid (512, 9), block 128.
__global__ __launch_bounds__(128) void qkv_kernel(
    const float* __restrict__ x, const float* __restrict__ Wqkv,
    const float* __restrict__ bqkv)
{
    __shared__ float As[32][132];   // [k][m], m-tile 128 (+4 pad)
    __shared__ float Bs[32][68];    // [k][n], n-tile 64 (+4 pad)

    const int mt = blockIdx.x, nt = blockIdx.y;
    const int tid = threadIdx.x;

    // --- A gather row (roll -2 + window map), one row per thread ---
    const int rowg = mt * 128 + tid;
    const int bw = rowg >> 6, tok = rowg & 63;
    const int b = bw >> 9, w = bw & 511;
    const int wz = w >> 6, wy = (w >> 3) & 7, wx = w & 7;
    const int tz = tok >> 4, tyy = (tok >> 2) & 3, txx = tok & 3;
    const int z  = (wz * 4 + tz  + 2) & 31;
    const int y  = (wy * 4 + tyy + 2) & 31;
    const int xx = (wx * 4 + txx + 2) & 31;
    const float4* __restrict__ xr4 =
        (const float4*)(x + ((((size_t)b * 32 + z) * 32 + y) * 32 + xx) * 192);

    // --- B load indices ---
    const int bcol  = (tid & 15) * 4;
    const int brow0 = tid >> 4;          // 0..7, rows brow0 + 8*i

    // --- compute coords ---
    const int r0 = (tid >> 3) * 8;       // 0..120
    const int c0 = (tid & 7) * 8;        // 0..56

    float acc[8][8] = {};
    float4 aR[8], bR[4];

    // prefetch chunk 0
    #pragma unroll
    for (int i = 0; i < 8; ++i) aR[i] = xr4[i];
    #pragma unroll
    for (int i = 0; i < 4; ++i)
        bR[i] = *(const float4*)&Wqkv[(size_t)(brow0 + 8 * i) * 576 + nt * 64 + bcol];

    for (int kc = 0; kc < 6; ++kc) {
        __syncthreads();
        // store staged chunk
        #pragma unroll
        for (int i = 0; i < 8; ++i) {
            As[i * 4 + 0][tid] = aR[i].x;
            As[i * 4 + 1][tid] = aR[i].y;
            As[i * 4 + 2][tid] = aR[i].z;
            As[i * 4 + 3][tid] = aR[i].w;
        }
        #pragma unroll
        for (int i = 0; i < 4; ++i)
            *(float4*)&Bs[brow0 + 8 * i][bcol] = bR[i];
        __syncthreads();
        // prefetch next chunk
        if (kc < 5) {
            #pragma unroll
            for (int i = 0; i < 8; ++i) aR[i] = xr4[(kc + 1) * 8 + i];
            #pragma unroll
            for (int i = 0; i < 4; ++i)
                bR[i] = *(const float4*)&Wqkv[(size_t)((kc + 1) * 32 + brow0 + 8 * i) * 576
                                              + nt * 64 + bcol];
        }
        // compute
        #pragma unroll 4
        for (int kk = 0; kk < 32; ++kk) {
            float a_r[8], b_r[8];
            *(float4*)&a_r[0] = *(float4*)&As[kk][r0];
            *(float4*)&a_r[4] = *(float4*)&As[kk][r0 + 4];
            *(float4*)&b_r[0] = *(float4*)&Bs[kk][c0];
            *(float4*)&b_r[4] = *(float4*)&Bs[kk][c0 + 4];
            #pragma unroll
            for (int i = 0; i < 8; ++i)
                #pragma unroll
                for (int j = 0; j < 8; ++j)
                    acc[i][j] += a_r[i] * b_r[j];
        }
    }

    // epilogue: rows mt*128 + r0..r0+7, cols nt*64 + c0..c0+7
    float4 bias0 = *(const float4*)&bqkv[nt * 64 + c0];
    float4 bias1 = *(const float4*)&bqkv[nt * 64 + c0 + 4];
    #pragma unroll
    for (int i = 0; i < 8; ++i) {
        size_t base = ((size_t)mt * 128 + r0 + i) * 576 + nt * 64 + c0;
        float4 o0 = { acc[i][0] + bias0.x, acc[i][1] + bias0.y,
                      acc[i][2] + bias0.z, acc[i][3] + bias0.w };
        float4 o1 = { acc[i][4] + bias1.x, acc[i][5] + bias1.y,
                      acc[i][6] + bias1.z, acc[i][7] + bias1.w };
        *(float4*)&g_qkv[base]     = o0;
        *(float4*)&g_qkv[base + 4] = o1;
    }
}

// ------------------------------ K2: attention ------------------------------
// grid (1024, 6), block 256. (unchanged from round 1)
__global__ __launch_bounds__(256) void attn_kernel(const float* __restrict__ relp)
{
    __shared__ float qkT[2 * 32 * 68];   // qT[32][68] | kT[32][68]; aliased as pT[64][66]
    __shared__ float vS[64 * 36];        // [q][c]
    __shared__ float simS[64 * 66];      // [p][q]
    __shared__ float relS[343];

    const int bw = blockIdx.x, h = blockIdx.y;
    const int w = bw & 511;
    const int wz = w >> 6, wy = (w >> 3) & 7, wx = w & 7;
    const int tid = threadIdx.x;
    const float scale = 0.17677669529663687f;   // 32^-0.5

    for (int i = tid; i < 343; i += 256) relS[i] = relp[h * 343 + i];

    {   // load q (transposed), k (transposed), v (row-major)
        int lane8 = tid & 7, rg = tid >> 3;
        int cc = lane8 * 4;
        #pragma unroll
        for (int pass = 0; pass < 2; ++pass) {
            int row = rg + pass * 32;
            size_t base = ((size_t)bw * 64 + row) * 576;
            float4 qv = *(const float4*)&g_qkv[base + h * 32 + cc];
            float4 kv = *(const float4*)&g_qkv[base + 192 + h * 32 + cc];
            float4 vv = *(const float4*)&g_qkv[base + 384 + h * 32 + cc];
            qkT[(cc + 0) * 68 + row] = qv.x;
            qkT[(cc + 1) * 68 + row] = qv.y;
            qkT[(cc + 2) * 68 + row] = qv.z;
            qkT[(cc + 3) * 68 + row] = qv.w;
            qkT[2176 + (cc + 0) * 68 + row] = kv.x;
            qkT[2176 + (cc + 1) * 68 + row] = kv.y;
            qkT[2176 + (cc + 2) * 68 + row] = kv.z;
            qkT[2176 + (cc + 3) * 68 + row] = kv.w;
            *(float4*)&vS[row * 36 + cc] = vv;
        }
    }
    __syncthreads();

    // phase 1: sim = q @ k^T, + bias, mask
    {
        int ty = tid >> 4, tx = tid & 15;
        int r0 = ty * 4, c0 = tx * 4;
        float acc[4][4] = {};
        #pragma unroll 4
        for (int kk = 0; kk < 32; ++kk) {
            float4 a  = *(float4*)&qkT[kk * 68 + r0];
            float4 bb = *(float4*)&qkT[2176 + kk * 68 + c0];
            acc[0][0] += a.x * bb.x; acc[0][1] += a.x * bb.y; acc[0][2] += a.x * bb.z; acc[0][3] += a.x * bb.w;
            acc[1][0] += a.y * bb.x; acc[1][1] += a.y * bb.y; acc[1][2] += a.y * bb.z; acc[1][3] += a.y * bb.w;
            acc[2][0] += a.z * bb.x; acc[2][1] += a.z * bb.y; acc[2][2] += a.z * bb.z; acc[2][3] += a.z * bb.w;
            acc[3][0] += a.w * bb.x; acc[3][1] += a.w * bb.y; acc[3][2] += a.w * bb.z; acc[3][3] += a.w * bb.w;
        }
        #pragma unroll
        for (int i = 0; i < 4; ++i) {
            int p = r0 + i;
            int pz = p >> 4, py = (p >> 2) & 3, px = p & 3;
            #pragma unroll
            for (int j = 0; j < 4; ++j) {
                int q = c0 + j;
                int qz = q >> 4, qy = (q >> 2) & 3, qx = q & 3;
                bool msk = (wz == 7 && ((pz < 2) != (qz < 2))) ||
                           (wy == 7 && ((py < 2) != (qy < 2))) ||
                           (wx == 7 && ((px < 2) != (qx < 2)));
                float bias = relS[((pz - qz + 3) * 7 + (py - qy + 3)) * 7 + (px - qx + 3)];
                simS[p * 66 + q] = msk ? -1e30f : acc[i][j] * scale + bias;
            }
        }
    }
    __syncthreads();

    // phase 2: softmax per row, write probs TRANSPOSED into qkT (pT[q][p], stride 66)
    {
        int warp = tid >> 5, lane = tid & 31;
        #pragma unroll
        for (int rr = 0; rr < 8; ++rr) {
            int r = warp * 8 + rr;
            float x0 = simS[r * 66 + lane];
            float x1 = simS[r * 66 + 32 + lane];
            float m = fmaxf(x0, x1);
            #pragma unroll
            for (int off = 16; off; off >>= 1)
                m = fmaxf(m, __shfl_xor_sync(0xffffffffu, m, off));
            float e0 = __expf(x0 - m), e1 = __expf(x1 - m);
            float s = e0 + e1;
            #pragma unroll
            for (int off = 16; off; off >>= 1)
                s += __shfl_xor_sync(0xffffffffu, s, off);
            float inv = 1.0f / s;
            qkT[lane * 66 + r]        = e0 * inv;
            qkT[(lane + 32) * 66 + r] = e1 * inv;
        }
    }
    __syncthreads();

    // phase 3: out = probs @ v  (64x32), thread tile 2x4
    {
        int ty3 = tid >> 3, tx3 = tid & 7;
        int p0 = ty3 * 2, cc = tx3 * 4;
        float o[2][4] = {};
        #pragma unroll 4
        for (int q = 0; q < 64; ++q) {
            float a0 = qkT[q * 66 + p0];
            float a1 = qkT[q * 66 + p0 + 1];
            float4 bv = *(float4*)&vS[q * 36 + cc];
            o[0][0] += a0 * bv.x; o[0][1] += a0 * bv.y; o[0][2] += a0 * bv.z; o[0][3] += a0 * bv.w;
            o[1][0] += a1 * bv.x; o[1][1] += a1 * bv.y; o[1][2] += a1 * bv.z; o[1][3] += a1 * bv.w;
        }
        #pragma unroll
        for (int i = 0; i < 2; ++i) {
            size_t base = ((size_t)bw * 64 + (p0 + i)) * 192 + h * 32 + cc;
            #pragma unroll
            for (int j = 0; j < 4; ++j) g_att[base + j] = o[i][j];
        }
    }
}

// ------------------------------ K3: out proj -------------------------------
// M=65536, K=192, N=192. grid (512, 3), block 128. Scatter epilogue (roll +2).
__global__ __launch_bounds__(128) void proj_kernel(
    const float* __restrict__ Wout, const float* __restrict__ bout,
    float* __restrict__ out)
{
    __shared__ float As[32][132];
    __shared__ float Bs[32][68];

    const int mt = blockIdx.x, nt = blockIdx.y;
    const int tid = threadIdx.x;

    const int rowg = mt * 128 + tid;
    const float4* __restrict__ ar4 = (const float4*)(g_att + (size_t)rowg * 192);

    const int bcol  = (tid & 15) * 4;
    const int brow0 = tid >> 4;

    const int r0 = (tid >> 3) * 8;
    const int c0 = (tid & 7) * 8;

    float acc[8][8] = {};
    float4 aR[8], bR[4];

    #pragma unroll
    for (int i = 0; i < 8; ++i) aR[i] = ar4[i];
    #pragma unroll
    for (int i = 0; i < 4; ++i)
        bR[i] = *(const float4*)&Wout[(size_t)(brow0 + 8 * i) * 192 + nt * 64 + bcol];

    for (int kc = 0; kc < 6; ++kc) {
        __syncthreads();
        #pragma unroll
        for (int i = 0; i < 8; ++i) {
            As[i * 4 + 0][tid] = aR[i].x;
            As[i * 4 + 1][tid] = aR[i].y;
            As[i * 4 + 2][tid] = aR[i].z;
            As[i * 4 + 3][tid] = aR[i].w;
        }
        #pragma unroll
        for (int i = 0; i < 4; ++i)
            *(float4*)&Bs[brow0 + 8 * i][bcol] = bR[i];
        __syncthreads();
        if (kc < 5) {
            #pragma unroll
            for (int i = 0; i < 8; ++i) aR[i] = ar4[(kc + 1) * 8 + i];
            #pragma unroll
            for (int i = 0; i < 4; ++i)
                bR[i] = *(const float4*)&Wout[(size_t)((kc + 1) * 32 + brow0 + 8 * i) * 192
                                              + nt * 64 + bcol];
        }
        #pragma unroll 4
        for (int kk = 0; kk < 32; ++kk) {
            float a_r[8], b_r[8];
            *(float4*)&a_r[0] = *(float4*)&As[kk][r0];
            *(float4*)&a_r[4] = *(float4*)&As[kk][r0 + 4];
            *(float4*)&b_r[0] = *(float4*)&Bs[kk][c0];
            *(float4*)&b_r[4] = *(float4*)&Bs[kk][c0 + 4];
            #pragma unroll
            for (int i = 0; i < 8; ++i)
                #pragma unroll
                for (int j = 0; j < 8; ++j)
                    acc[i][j] += a_r[i] * b_r[j];
        }
    }

    // epilogue: scatter with inverse window map + roll(+2)
    float4 bias0 = *(const float4*)&bout[nt * 64 + c0];
    float4 bias1 = *(const float4*)&bout[nt * 64 + c0 + 4];
    #pragma unroll
    for (int i = 0; i < 8; ++i) {
        int rg = mt * 128 + r0 + i;
        int bw = rg >> 6, tok = rg & 63;
        int b = bw >> 9, w = bw & 511;
        int wz = w >> 6, wy = (w >> 3) & 7, wx = w & 7;
        int tz = tok >> 4, tyy = (tok >> 2) & 3, txx = tok & 3;
        int z  = (wz * 4 + tz  + 2) & 31;
        int y  = (wy * 4 + tyy + 2) & 31;
        int xx = (wx * 4 + txx + 2) & 31;
        size_t base = ((((size_t)b * 32 + z) * 32 + y) * 32 + xx) * 192 + nt * 64 + c0;
        float4 o0 = { acc[i][0] + bias0.x, acc[i][1] + bias0.y,
                      acc[i][2] + bias0.z, acc[i][3] + bias0.w };
        float4 o1 = { acc[i][4] + bias1.x, acc[i][5] + bias1.y,
                      acc[i][6] + bias1.z, acc[i][7] + bias1.w };
        *(float4*)&out[base]     = o0;
        *(float4*)&out[base + 4] = o1;
    }
}

// ------------------------------- launch ------------------------------------
extern "C" void kernel_launch(void* const* d_in, const int* in_sizes, int n_in,
                              void* d_out, int out_size)
{
    const float* x    = (const float*)d_in[0];
    const float* Wqkv = (const float*)d_in[1];
    const float* bqkv = (const float*)d_in[2];
    const float* relp = (const float*)d_in[3];
    const float* Wout = (const float*)d_in[4];
    const float* bout = (const float*)d_in[5];
    float* out = (float*)d_out;

    qkv_kernel<<<dim3(512, 9), 128>>>(x, Wqkv, bqkv);
    attn_kernel<<<dim3(1024, 6), 256>>>(relp);
    proj_kernel<<<dim3(512, 3), 128>>>(Wout, bout, out);
}

// round 8
// speedup vs baseline: 1.7100x; 1.5465x over previous
#include <cuda_runtime.h>
#include <cuda_bf16.h>
#include <cstdint>

// ---------------------------------------------------------------------------
// WMSA round 7: round-6 design with the prefetch chunk-stride bug fixed
// (uint4 chunk stride is 4, not 2). GEMMs on warp-level mma.sync bf16
// (x3 split emulation of fp32), compiles for plain sm_103.
// ---------------------------------------------------------------------------

#define NWINS 1024
#define TPW   64

__device__ float g_qkv[(size_t)NWINS * TPW * 576];
__device__ __align__(16) __nv_bfloat16 g_xs_hi[(size_t)NWINS * TPW * 192];
__device__ __align__(16) __nv_bfloat16 g_xs_lo[(size_t)NWINS * TPW * 192];
__device__ __align__(16) __nv_bfloat16 g_at_hi[(size_t)NWINS * TPW * 192];
__device__ __align__(16) __nv_bfloat16 g_at_lo[(size_t)NWINS * TPW * 192];

// split weights, transposed to [n][k]
__device__ __align__(16) __nv_bfloat16 WqkvT_hi[576 * 192];
__device__ __align__(16) __nv_bfloat16 WqkvT_lo[576 * 192];
__device__ __align__(16) __nv_bfloat16 WoutT_hi[192 * 192];
__device__ __align__(16) __nv_bfloat16 WoutT_lo[192 * 192];

// ------------------------------ helpers ------------------------------------
__device__ __forceinline__ uint32_t smem_u32(const void* p) {
    uint32_t a;
    asm("{ .reg .u64 t; cvta.to.shared.u64 t, %1; cvt.u32.u64 %0, t; }" : "=r"(a) : "l"(p));
    return a;
}
__device__ __forceinline__ uint32_t pack2(float a, float b) {   // mem order: a(lo), b(hi)
    uint32_t r;
    asm("cvt.rn.bf16x2.f32 %0, %1, %2;" : "=r"(r) : "f"(b), "f"(a));
    return r;
}
__device__ __forceinline__ void split2(float a, float b, uint32_t& h, uint32_t& l) {
    h = pack2(a, b);
    float ha = __uint_as_float(h << 16);
    float hb = __uint_as_float(h & 0xffff0000u);
    l = pack2(a - ha, b - hb);
}
__device__ __forceinline__ void ldsm_x4(uint32_t* r, uint32_t addr) {
    asm volatile("ldmatrix.sync.aligned.m8n8.x4.shared.b16 {%0,%1,%2,%3}, [%4];"
        : "=r"(r[0]), "=r"(r[1]), "=r"(r[2]), "=r"(r[3]) : "r"(addr));
}
__device__ __forceinline__ void mma_bf16(float* c, const uint32_t* a, const uint32_t* b) {
    asm volatile("mma.sync.aligned.m16n8k16.row.col.f32.bf16.bf16.f32 "
        "{%0,%1,%2,%3}, {%4,%5,%6,%7}, {%8,%9}, {%0,%1,%2,%3};"
        : "+f"(c[0]), "+f"(c[1]), "+f"(c[2]), "+f"(c[3])
        : "r"(a[0]), "r"(a[1]), "r"(a[2]), "r"(a[3]), "r"(b[0]), "r"(b[1]));
}

// ------------------------------ prep: weights ------------------------------
__global__ void prep_kernel(const float* __restrict__ Wqkv,
                            const float* __restrict__ Wout)
{
    int i = blockIdx.x * 256 + threadIdx.x;
    if (i < 576 * 192) {
        int n = i / 192, k = i % 192;
        float v = Wqkv[(size_t)k * 576 + n];
        __nv_bfloat16 h = __float2bfloat16(v);
        WqkvT_hi[i] = h;
        WqkvT_lo[i] = __float2bfloat16(v - __bfloat162float(h));
    }
    int j = i - 576 * 192;
    if (j >= 0 && j < 192 * 192) {
        int n = j / 192, k = j % 192;
        float v = Wout[(size_t)k * 192 + n];
        __nv_bfloat16 h = __float2bfloat16(v);
        WoutT_hi[j] = h;
        WoutT_lo[j] = __float2bfloat16(v - __bfloat162float(h));
    }
}

// ------------------------------ convert x ----------------------------------
// grid 4096, block 256. 16 rows/block, 16 threads/row, 12 floats/thread.
__global__ __launch_bounds__(256) void convx_kernel(const float* __restrict__ x)
{
    const int t = threadIdx.x;
    const int row = blockIdx.x * 16 + (t >> 4);
    const int l16 = t & 15;
    const int tok = row & 63, bw = row >> 6;
    const int b = bw >> 9, w = bw & 511;
    const int z  = (((w >> 6) << 2)       + (tok >> 4)       + 2) & 31;
    const int y  = ((((w >> 3) & 7) << 2) + ((tok >> 2) & 3) + 2) & 31;
    const int xx = (((w & 7) << 2)        + (tok & 3)        + 2) & 31;
    const float* src = x + ((((size_t)b * 32 + z) * 32 + y) * 32 + xx) * 192 + l16 * 12;
    const size_t dst = (size_t)row * 192 + l16 * 12;
    #pragma unroll
    for (int i = 0; i < 3; ++i) {
        float4 v = *(const float4*)(src + i * 4);
        uint32_t h0, l0, h1, l1;
        split2(v.x, v.y, h0, l0);
        split2(v.z, v.w, h1, l1);
        *(uint2*)&g_xs_hi[dst + i * 4] = make_uint2(h0, h1);
        *(uint2*)&g_xs_lo[dst + i * 4] = make_uint2(l0, l1);
    }
}

// ------------------------------ GEMM core ----------------------------------
// 256 threads, tile 128(m) x 64(n), warp tile 32x32, K in 6 chunks of 32.
// SMEM rows padded to 40 bf16 (80 B) -> conflict-free ldmatrix phases.

struct GemmSmem {
    __nv_bfloat16 AH[128 * 40];
    __nv_bfloat16 AL[128 * 40];
    __nv_bfloat16 BH[64 * 40];
    __nv_bfloat16 BL[64 * 40];
};

template <int KTOT>
__device__ __forceinline__ void gemm_mainloop(
    const __nv_bfloat16* __restrict__ gAh, const __nv_bfloat16* __restrict__ gAl,
    const __nv_bfloat16* __restrict__ gBh, const __nv_bfloat16* __restrict__ gBl,
    GemmSmem* sm, float acc[2][4][4])
{
    const int tid = threadIdx.x, lane = tid & 31, wid = tid >> 5;
    const int m0 = (wid & 3) * 32, n0 = (wid >> 2) * 32;
    const int half = tid & 1;
    const int arow = tid >> 1;          // 0..127
    const int brow = (tid >> 1) & 63;   // 0..63 (tid<128 loads B)

    const uint4* gA_h = (const uint4*)(gAh + (size_t)arow * KTOT + half * 16);
    const uint4* gA_l = (const uint4*)(gAl + (size_t)arow * KTOT + half * 16);
    const uint4* gB_h = (const uint4*)(gBh + (size_t)brow * 192 + half * 16);
    const uint4* gB_l = (const uint4*)(gBl + (size_t)brow * 192 + half * 16);

    const uint32_t sAH = smem_u32(sm->AH), sAL = smem_u32(sm->AL);
    const uint32_t sBH = smem_u32(sm->BH), sBL = smem_u32(sm->BL);

    uint4 aPh[2], aPl[2], bPh[2], bPl[2];
    aPh[0] = gA_h[0]; aPh[1] = gA_h[1];
    aPl[0] = gA_l[0]; aPl[1] = gA_l[1];
    if (tid < 128) {
        bPh[0] = gB_h[0]; bPh[1] = gB_h[1];
        bPl[0] = gB_l[0]; bPl[1] = gB_l[1];
    }

    for (int kc = 0; kc < 6; ++kc) {
        __syncthreads();
        {
            *(uint4*)&sm->AH[arow * 40 + half * 16]     = aPh[0];
            *(uint4*)&sm->AH[arow * 40 + half * 16 + 8] = aPh[1];
            *(uint4*)&sm->AL[arow * 40 + half * 16]     = aPl[0];
            *(uint4*)&sm->AL[arow * 40 + half * 16 + 8] = aPl[1];
            if (tid < 128) {
                *(uint4*)&sm->BH[brow * 40 + half * 16]     = bPh[0];
                *(uint4*)&sm->BH[brow * 40 + half * 16 + 8] = bPh[1];
                *(uint4*)&sm->BL[brow * 40 + half * 16]     = bPl[0];
                *(uint4*)&sm->BL[brow * 40 + half * 16 + 8] = bPl[1];
            }
        }
        __syncthreads();
        if (kc < 5) {
            int o = (kc + 1) * 4;   // FIXED: 32 bf16 chunk = 4 uint4 (was *2)
            aPh[0] = gA_h[o]; aPh[1] = gA_h[o + 1];
            aPl[0] = gA_l[o]; aPl[1] = gA_l[o + 1];
            if (tid < 128) {
                bPh[0] = gB_h[o]; bPh[1] = gB_h[o + 1];
                bPl[0] = gB_l[o]; bPl[1] = gB_l[o + 1];
            }
        }
        #pragma unroll
        for (int ks = 0; ks < 2; ++ks) {
            uint32_t aH[2][4], aL[2][4], bH[8], bL[8];
            #pragma unroll
            for (int mf = 0; mf < 2; ++mf) {
                uint32_t off = (uint32_t)((m0 + mf * 16 + (lane & 15)) * 80
                                          + (ks * 2 + (lane >> 4)) * 16);
                ldsm_x4(aH[mf], sAH + off);
                ldsm_x4(aL[mf], sAL + off);
            }
            #pragma unroll
            for (int nf = 0; nf < 2; ++nf) {
                uint32_t off = (uint32_t)((n0 + nf * 16 + ((lane >> 4) & 1) * 8 + (lane & 7)) * 80
                                          + (ks * 2 + ((lane >> 3) & 1)) * 16);
                ldsm_x4(&bH[nf * 4], sBH + off);
                ldsm_x4(&bL[nf * 4], sBL + off);
            }
            #pragma unroll
            for (int mf = 0; mf < 2; ++mf)
                #pragma unroll
                for (int j = 0; j < 4; ++j) {
                    mma_bf16(acc[mf][j], aH[mf], &bH[j * 2]);
                    mma_bf16(acc[mf][j], aH[mf], &bL[j * 2]);
                    mma_bf16(acc[mf][j], aL[mf], &bH[j * 2]);
                }
        }
    }
}

// ------------------------------ K1: QKV ------------------------------------
// grid (512, 9), block 256.
__global__ __launch_bounds__(256) void qkv_mma(const float* __restrict__ bqkv)
{
    __shared__ GemmSmem sm;
    const int tid = threadIdx.x, lane = tid & 31, wid = tid >> 5;
    const int mt = blockIdx.x, nt = blockIdx.y;
    const int m0 = (wid & 3) * 32, n0 = (wid >> 2) * 32;

    float acc[2][4][4] = {};
    gemm_mainloop<192>(
        g_xs_hi + (size_t)mt * 128 * 192, g_xs_lo + (size_t)mt * 128 * 192,
        WqkvT_hi + (size_t)nt * 64 * 192, WqkvT_lo + (size_t)nt * 64 * 192,
        &sm, acc);

    const int rbase = mt * 128 + m0 + (lane >> 2);
    #pragma unroll
    for (int j = 0; j < 4; ++j) {
        int col = nt * 64 + n0 + j * 8 + (lane & 3) * 2;
        float b0 = __ldg(&bqkv[col]), b1 = __ldg(&bqkv[col + 1]);
        #pragma unroll
        for (int mf = 0; mf < 2; ++mf) {
            size_t r0 = (size_t)(rbase + mf * 16) * 576 + col;
            size_t r1 = (size_t)(rbase + mf * 16 + 8) * 576 + col;
            *(float2*)&g_qkv[r0] = make_float2(acc[mf][j][0] + b0, acc[mf][j][1] + b1);
            *(float2*)&g_qkv[r1] = make_float2(acc[mf][j][2] + b0, acc[mf][j][3] + b1);
        }
    }
}

// ------------------------------ K2: attention ------------------------------
// grid (1024, 6), block 256. Output written as bf16 hi/lo planes.
__global__ __launch_bounds__(256) void attn_kernel(const float* __restrict__ relp)
{
    __shared__ float qkT[2 * 32 * 68];
    __shared__ float vS[64 * 36];
    __shared__ float simS[64 * 66];
    __shared__ float relS[343];

    const int bw = blockIdx.x, h = blockIdx.y;
    const int w = bw & 511;
    const int wz = w >> 6, wy = (w >> 3) & 7, wx = w & 7;
    const int tid = threadIdx.x;
    const float scale = 0.17677669529663687f;

    for (int i = tid; i < 343; i += 256) relS[i] = relp[h * 343 + i];

    {
        int lane8 = tid & 7, rg = tid >> 3;
        int cc = lane8 * 4;
        #pragma unroll
        for (int pass = 0; pass < 2; ++pass) {
            int row = rg + pass * 32;
            size_t base = ((size_t)bw * 64 + row) * 576;
            float4 qv = *(const float4*)&g_qkv[base + h * 32 + cc];
            float4 kv = *(const float4*)&g_qkv[base + 192 + h * 32 + cc];
            float4 vv = *(const float4*)&g_qkv[base + 384 + h * 32 + cc];
            qkT[(cc + 0) * 68 + row] = qv.x;
            qkT[(cc + 1) * 68 + row] = qv.y;
            qkT[(cc + 2) * 68 + row] = qv.z;
            qkT[(cc + 3) * 68 + row] = qv.w;
            qkT[2176 + (cc + 0) * 68 + row] = kv.x;
            qkT[2176 + (cc + 1) * 68 + row] = kv.y;
            qkT[2176 + (cc + 2) * 68 + row] = kv.z;
            qkT[2176 + (cc + 3) * 68 + row] = kv.w;
            *(float4*)&vS[row * 36 + cc] = vv;
        }
    }
    __syncthreads();

    {
        int ty = tid >> 4, tx = tid & 15;
        int r0 = ty * 4, c0 = tx * 4;
        float acc[4][4] = {};
        #pragma unroll 4
        for (int kk = 0; kk < 32; ++kk) {
            float4 a  = *(float4*)&qkT[kk * 68 + r0];
            float4 bb = *(float4*)&qkT[2176 + kk * 68 + c0];
            acc[0][0] += a.x * bb.x; acc[0][1] += a.x * bb.y; acc[0][2] += a.x * bb.z; acc[0][3] += a.x * bb.w;
            acc[1][0] += a.y * bb.x; acc[1][1] += a.y * bb.y; acc[1][2] += a.y * bb.z; acc[1][3] += a.y * bb.w;
            acc[2][0] += a.z * bb.x; acc[2][1] += a.z * bb.y; acc[2][2] += a.z * bb.z; acc[2][3] += a.z * bb.w;
            acc[3][0] += a.w * bb.x; acc[3][1] += a.w * bb.y; acc[3][2] += a.w * bb.z; acc[3][3] += a.w * bb.w;
        }
        #pragma unroll
        for (int i = 0; i < 4; ++i) {
            int p = r0 + i;
            int pz = p >> 4, py = (p >> 2) & 3, px = p & 3;
            #pragma unroll
            for (int j = 0; j < 4; ++j) {
                int q = c0 + j;
                int qz = q >> 4, qy = (q >> 2) & 3, qx = q & 3;
                bool msk = (wz == 7 && ((pz < 2) != (qz < 2))) ||
                           (wy == 7 && ((py < 2) != (qy < 2))) ||
                           (wx == 7 && ((px < 2) != (qx < 2)));
                float bias = relS[((pz - qz + 3) * 7 + (py - qy + 3)) * 7 + (px - qx + 3)];
                simS[p * 66 + q] = msk ? -1e30f : acc[i][j] * scale + bias;
            }
        }
    }
    __syncthreads();

    {
        int warp = tid >> 5, lane = tid & 31;
        #pragma unroll
        for (int rr = 0; rr < 8; ++rr) {
            int r = warp * 8 + rr;
            float x0 = simS[r * 66 + lane];
            float x1 = simS[r * 66 + 32 + lane];
            float m = fmaxf(x0, x1);
            #pragma unroll
            for (int off = 16; off; off >>= 1)
                m = fmaxf(m, __shfl_xor_sync(0xffffffffu, m, off));
            float e0 = __expf(x0 - m), e1 = __expf(x1 - m);
            float s = e0 + e1;
            #pragma unroll
            for (int off = 16; off; off >>= 1)
                s += __shfl_xor_sync(0xffffffffu, s, off);
            float inv = 1.0f / s;
            qkT[lane * 66 + r]        = e0 * inv;
            qkT[(lane + 32) * 66 + r] = e1 * inv;
        }
    }
    __syncthreads();

    {
        int ty3 = tid >> 3, tx3 = tid & 7;
        int p0 = ty3 * 2, cc = tx3 * 4;
        float o[2][4] = {};
        #pragma unroll 4
        for (int q = 0; q < 64; ++q) {
            float a0 = qkT[q * 66 + p0];
            float a1 = qkT[q * 66 + p0 + 1];
            float4 bv = *(float4*)&vS[q * 36 + cc];
            o[0][0] += a0 * bv.x; o[0][1] += a0 * bv.y; o[0][2] += a0 * bv.z; o[0][3] += a0 * bv.w;
            o[1][0] += a1 * bv.x; o[1][1] += a1 * bv.y; o[1][2] += a1 * bv.z; o[1][3] += a1 * bv.w;
        }
        #pragma unroll
        for (int i = 0; i < 2; ++i) {
            size_t base = ((size_t)bw * 64 + (p0 + i)) * 192 + h * 32 + cc;
            uint32_t h0, l0, h1, l1;
            split2(o[i][0], o[i][1], h0, l0);
            split2(o[i][2], o[i][3], h1, l1);
            *(uint2*)&g_at_hi[base] = make_uint2(h0, h1);
            *(uint2*)&g_at_lo[base] = make_uint2(l0, l1);
        }
    }
}

// ------------------------------ K3: out proj -------------------------------
// grid (512, 3), block 256. Scatter epilogue (inverse window + roll +2).
__global__ __launch_bounds__(256) void proj_mma(
    const float* __restrict__ bout, float* __restrict__ out)
{
    __shared__ GemmSmem sm;
    const int tid = threadIdx.x, lane = tid & 31, wid = tid >> 5;
    const int mt = blockIdx.x, nt = blockIdx.y;
    const int m0 = (wid & 3) * 32, n0 = (wid >> 2) * 32;

    float acc[2][4][4] = {};
    gemm_mainloop<192>(
        g_at_hi + (size_t)mt * 128 * 192, g_at_lo + (size_t)mt * 128 * 192,
        WoutT_hi + (size_t)nt * 64 * 192, WoutT_lo + (size_t)nt * 64 * 192,
        &sm, acc);

    size_t obase[2][2];
    #pragma unroll
    for (int mf = 0; mf < 2; ++mf)
        #pragma unroll
        for (int rr = 0; rr < 2; ++rr) {
            int rg = mt * 128 + m0 + mf * 16 + rr * 8 + (lane >> 2);
            int tok = rg & 63, bw = rg >> 6;
            int b = bw >> 9, w = bw & 511;
            int z  = (((w >> 6) << 2)       + (tok >> 4)       + 2) & 31;
            int y  = ((((w >> 3) & 7) << 2) + ((tok >> 2) & 3) + 2) & 31;
            int xx = (((w & 7) << 2)        + (tok & 3)        + 2) & 31;
            obase[mf][rr] = ((((size_t)b * 32 + z) * 32 + y) * 32 + xx) * 192;
        }

    #pragma unroll
    for (int j = 0; j < 4; ++j) {
        int col = nt * 64 + n0 + j * 8 + (lane & 3) * 2;
        float b0 = __ldg(&bout[col]), b1 = __ldg(&bout[col + 1]);
        #pragma unroll
        for (int mf = 0; mf < 2; ++mf) {
            *(float2*)&out[obase[mf][0] + col] =
                make_float2(acc[mf][j][0] + b0, acc[mf][j][1] + b1);
            *(float2*)&out[obase[mf][1] + col] =
                make_float2(acc[mf][j][2] + b0, acc[mf][j][3] + b1);
        }
    }
}

// ------------------------------- launch ------------------------------------
extern "C" void kernel_launch(void* const* d_in, const int* in_sizes, int n_in,
                              void* d_out, int out_size)
{
    const float* x    = (const float*)d_in[0];
    const float* Wqkv = (const float*)d_in[1];
    const float* bqkv = (const float*)d_in[2];
    const float* relp = (const float*)d_in[3];
    const float* Wout = (const float*)d_in[4];
    const float* bout = (const float*)d_in[5];
    float* out = (float*)d_out;

    prep_kernel<<<576, 256>>>(Wqkv, Wout);
    convx_kernel<<<4096, 256>>>(x);
    qkv_mma<<<dim3(512, 9), 256>>>(bqkv);
    attn_kernel<<<dim3(1024, 6), 256>>>(relp);
    proj_mma<<<dim3(512, 3), 256>>>(bout, out);
}